// round 11
// baseline (speedup 1.0000x reference)
#include <cuda_runtime.h>
#include <cuda_fp16.h>
#include <math.h>
#include <stdint.h>

#define H_ 128
#define W_ 256
#define C_ 64
#define F_ 128
#define B_ 4
#define IH 130
#define IW 258

#define NTHREADS 384   // 8 consumer warps (MMA) + 4 producer warps (gather)

// ---------------- device scratch ----------------
__device__ int   g_y0t[H_ * 9];
__device__ int   g_y1t[H_ * 9];
__device__ float g_wyT[H_ * 9];
__device__ float g_wyB[H_ * 9];
__device__ float g_offx[H_ * 9];
// B fragments in mma.m16n8k16 register order: [tap][ks][n8][lane] -> uint2 {b0,b1}, fp16
__device__ uint2 g_bh[9 * 4 * 16 * 32];
__device__ uint2 g_bl[9 * 4 * 16 * 32];

// ---------------- helpers ----------------
__device__ __forceinline__ uint32_t smem_u32(const void* p) {
    uint32_t a;
    asm("{ .reg .u64 t; cvta.to.shared.u64 t, %1; cvt.u32.u64 %0, t; }" : "=r"(a) : "l"(p));
    return a;
}
__device__ __forceinline__ uint32_t pack_half2(__half lo, __half hi) {
    return ((uint32_t)__half_as_ushort(hi) << 16) | __half_as_ushort(lo);
}
__device__ __forceinline__ void ldsm_x4(uint32_t* r, uint32_t addr) {
    asm volatile("ldmatrix.sync.aligned.m8n8.x4.shared.b16 {%0,%1,%2,%3}, [%4];"
                 : "=r"(r[0]), "=r"(r[1]), "=r"(r[2]), "=r"(r[3]) : "r"(addr));
}
__device__ __forceinline__ void mma_f16(float* d, const uint32_t* a, uint32_t b0, uint32_t b1) {
    asm volatile(
        "mma.sync.aligned.m16n8k16.row.col.f32.f16.f16.f32 "
        "{%0,%1,%2,%3}, {%4,%5,%6,%7}, {%8,%9}, {%0,%1,%2,%3};"
        : "+f"(d[0]), "+f"(d[1]), "+f"(d[2]), "+f"(d[3])
        : "r"(a[0]), "r"(a[1]), "r"(a[2]), "r"(a[3]), "r"(b0), "r"(b1));
}
#define BAR_SYNC(id, cnt)   asm volatile("bar.sync %0, %1;"   :: "r"(id), "r"(cnt) : "memory")
#define BAR_ARRIVE(id, cnt) asm volatile("bar.arrive %0, %1;" :: "r"(id), "r"(cnt) : "memory")
#define MEMBAR_CTA()        asm volatile("membar.cta;" ::: "memory")

// barrier ids: full[buf] = 1+buf, empty[buf] = 3+buf, producer-param = 5

// ---------------- combined init: B fragments (blocks 0..71) + distortion tables (block 72) ----
__global__ void init_kernel(const float* __restrict__ wk) {
    if (blockIdx.x < 72) {
        int idx = blockIdx.x * 256 + threadIdx.x;   // < 18432
        int lane = idx & 31;
        int n8 = (idx >> 5) & 15;
        int ks = (idx >> 9) & 3;
        int tap = idx >> 11;
        int g = lane >> 2, tg = lane & 3;
        int n = n8 * 8 + g;
        int kb = ks * 16 + 2 * tg;
        float w0 = wk[(size_t)(tap * 64 + kb) * 128 + n];
        float w1 = wk[(size_t)(tap * 64 + kb + 1) * 128 + n];
        float w2 = wk[(size_t)(tap * 64 + kb + 8) * 128 + n];
        float w3 = wk[(size_t)(tap * 64 + kb + 9) * 128 + n];
        __half h0 = __float2half_rn(w0), h1 = __float2half_rn(w1);
        __half h2 = __float2half_rn(w2), h3 = __float2half_rn(w3);
        g_bh[idx] = make_uint2(pack_half2(h0, h1), pack_half2(h2, h3));
        __half l0 = __float2half_rn(w0 - __half2float(h0));
        __half l1 = __float2half_rn(w1 - __half2float(h1));
        __half l2 = __float2half_rn(w2 - __half2float(h2));
        __half l3 = __float2half_rn(w3 - __half2float(h3));
        g_bl[idx] = make_uint2(pack_half2(l0, l1), pack_half2(l2, l3));
        return;
    }
    // ---- distortion tables (branch-free analytic fp32, see R7) ----
    for (int idx = threadIdx.x; idx < H_ * 9; idx += 256) {
        int h = idx / 9, k = idx % 9;
        const float pi = 3.14159265358979323846f;
        float unit_w = 2.0f * pi / (float)W_;
        float unit_h = pi / (2.0f * (float)H_);
        float rho = tanf(unit_w);
        float phi = ((float)H_ - (float)h) * unit_h;
        float s = sinf(phi), c = cosf(phi);
        const int ra[9] = { 1, 1, 1, 0, 0, 0, -1, -1, -1 };
        const int rb[9] = { -1, 0, 1, -1, 0, 1, -1, 0, 1 };
        float a = (float)ra[k], b = (float)rb[k];
        float t = (-rho * a) / (1.0f - rho * b * s);
        float t2 = t * t;
        float at = t * (1.0f - t2 * (1.0f / 3.0f) + t2 * t2 * (1.0f / 5.0f));
        float off_to_y = at * ((float)W_ / (2.0f * pi));
        float rb1 = rho * b;
        float eps = rb1 * c * (1.0f
                  + rb1 * s * 0.5f
                  + rb1 * rb1 * (1.0f + 2.0f * s * s) * (1.0f / 6.0f)
                  + rb1 * rb1 * rb1 * s * (9.0f + 6.0f * s * s) * (1.0f / 24.0f));
        float off_to_x = -(2.0f * (float)H_ / pi) * eps;

        int dy = k / 3;
        float yf = (float)(h + dy) + off_to_y;
        yf = fminf(fmaxf(yf, 0.0f), (float)(IH - 1));
        int y0 = (int)floorf(yf);
        int y1 = y0 + 1;
        y0 = max(0, min(y0, IH - 1));
        y1 = max(0, min(y1, IH - 1));
        g_y0t[idx] = y0;
        g_y1t[idx] = y1;
        g_wyT[idx] = (float)y1 - yf;
        g_wyB[idx] = yf - (float)y0;
        g_offx[idx] = off_to_x;
    }
}

// ---------------- main fused kernel: warp-specialized producer/consumer ----------------
// CTA: 128 pixels x 128 F. Warps 0-7: MMA consumers (warp tile 64x32).
// Warps 8-11: gather producers. Double-buffered A tile AND param tables (same buf):
//   producer(k): [k>=2: sync empty[buf]] -> params[buf] -> bar5 -> gather A[buf] -> membar -> arrive full[buf]
//   consumer(k): sync full[buf] -> MMA -> arrive empty[buf]
// params[buf] reuse at tap k+2 is fenced by empty[buf]: all producers reach that sync
// only after completing the tap-k gather (their last readers of params[buf]).
__global__ __launch_bounds__(NTHREADS, 1) void distconv_mma(
    const float* __restrict__ inp,
    const float* __restrict__ bias,
    float* __restrict__ out)
{
    __shared__ __align__(128) unsigned char sA[2][16384];  // fp16 A tiles, ldmatrix-swizzled
    __shared__ float4 s_w[2][128];   // per-pixel bilinear weights (pad corners zeroed)
    __shared__ int4   s_a[2][128];   // per-pixel corner byte offsets

    const int tid = threadIdx.x;
    const int wid = tid >> 5, lane = tid & 31;

    const int b = blockIdx.z, h = blockIdx.y;
    const int w0 = blockIdx.x * 128;

    if (wid >= 8) {
        // ================= PRODUCER (warps 8-11, 128 threads) =================
        const char* inpC = (const char*)(inp + (size_t)b * (H_ * W_ * C_));
        const int tp = tid - 256;           // 0..127
        const int chunk = tp & 15;
        const int pgrp = tp >> 4;           // 0..7
        const int cb = chunk * 16;
        const int chalf = (chunk & 1) * 8;
        const int cpair = chunk >> 1;

        for (int k = 0; k < 9; ++k) {
            const int buf = k & 1;
            if (k >= 2) BAR_SYNC(3 + buf, NTHREADS);   // consumers done with buffer AND
                                                       // all producers done reading params[buf]

            // ---- params: one pixel per producer thread (buffer buf) ----
            {
                int t9 = h * 9 + k;
                int dxk = k - (k / 3) * 3;
                float x = (float)(w0 + tp + dxk) + g_offx[t9];
                if (x < 0.f) x += (float)IW;
                if (x > (float)(IW - 1)) x -= (float)IW;
                int x0 = (int)floorf(x);
                int x1 = x0 + 1;
                x0 = max(0, min(x0, IW - 1));
                x1 = max(0, min(x1, IW - 1));
                float wxl = (float)x1 - x, wxr = x - (float)x0;
                int y0 = g_y0t[t9], y1 = g_y1t[t9];
                float wyT = g_wyT[t9], wyB = g_wyB[t9];
                bool vy0 = (y0 >= 1) && (y0 <= H_);
                bool vy1 = (y1 >= 1) && (y1 <= H_);
                bool vx0 = (x0 >= 1) && (x0 <= W_);
                bool vx1 = (x1 >= 1) && (x1 <= W_);
                float4 wv;
                int4 av;
                wv.x = (vy0 && vx0) ? wyT * wxl : 0.f;
                wv.y = (vy0 && vx1) ? wyT * wxr : 0.f;
                wv.z = (vy1 && vx0) ? wyB * wxl : 0.f;
                wv.w = (vy1 && vx1) ? wyB * wxr : 0.f;
                av.x = (vy0 && vx0) ? ((y0 - 1) * W_ + (x0 - 1)) * 256 : 0;
                av.y = (vy0 && vx1) ? ((y0 - 1) * W_ + (x1 - 1)) * 256 : 0;
                av.z = (vy1 && vx0) ? ((y1 - 1) * W_ + (x0 - 1)) * 256 : 0;
                av.w = (vy1 && vx1) ? ((y1 - 1) * W_ + (x1 - 1)) * 256 : 0;
                s_w[buf][tp] = wv;
                s_a[buf][tp] = av;
            }
            BAR_SYNC(5, 128);   // params[buf] visible to all producers

            // ---- gather: coalesced bilinear blend -> fp16 swizzled smem ----
            unsigned char* sAc = sA[buf];
#pragma unroll
            for (int it = 0; it < 16; ++it) {
                int p = it * 8 + pgrp;
                float4 wv = s_w[buf][p];
                int4 av = s_a[buf][p];
                float4 q0 = *(const float4*)(inpC + av.x + cb);
                float4 q1 = *(const float4*)(inpC + av.y + cb);
                float4 q2 = *(const float4*)(inpC + av.z + cb);
                float4 q3 = *(const float4*)(inpC + av.w + cb);
                float v0 = wv.x * q0.x + wv.y * q1.x + wv.z * q2.x + wv.w * q3.x;
                float v1 = wv.x * q0.y + wv.y * q1.y + wv.z * q2.y + wv.w * q3.y;
                float v2 = wv.x * q0.z + wv.y * q1.z + wv.z * q2.z + wv.w * q3.z;
                float v3 = wv.x * q0.w + wv.y * q1.w + wv.z * q2.w + wv.w * q3.w;
                __half2 hA = __floats2half2_rn(v0, v1);
                __half2 hB = __floats2half2_rn(v2, v3);
                uint32_t addr = (uint32_t)p * 128 + ((uint32_t)(cpair ^ (p & 7)) << 4) + chalf;
                *(uint2*)(sAc + addr) = make_uint2(*(uint32_t*)&hA, *(uint32_t*)&hB);
            }
            MEMBAR_CTA();
            BAR_ARRIVE(1 + buf, NTHREADS);   // A[buf] full
        }
        return;
    }

    // ================= CONSUMER (warps 0-7, 256 threads) =================
    const int warp_m = wid >> 2, warp_n = wid & 3;
    const int g = lane >> 2, tg = lane & 3;

    const uint32_t aA0 = smem_u32(sA[0]), aA1 = smem_u32(sA[1]);
    const uint32_t rowoff = (uint32_t)(warp_m * 64 + (lane & 15)) * 128;
    const int rlo = lane & 7;
    const int khalf = lane >> 4;

    float acc[4][4][4];
#pragma unroll
    for (int mi = 0; mi < 4; ++mi)
#pragma unroll
        for (int ni = 0; ni < 4; ++ni)
#pragma unroll
            for (int q = 0; q < 4; ++q) acc[mi][ni][q] = 0.f;

    for (int k = 0; k < 9; ++k) {
        const int buf = k & 1;
        BAR_SYNC(1 + buf, NTHREADS);   // wait A[buf] full
        const uint32_t aA = buf ? aA1 : aA0;
#pragma unroll
        for (int ks = 0; ks < 4; ++ks) {
            uint2 BH[4], BL[4];
            int bidx = ((k * 4 + ks) * 16 + warp_n * 4) * 32 + lane;
#pragma unroll
            for (int ni = 0; ni < 4; ++ni) {
                BH[ni] = g_bh[bidx + ni * 32];
                BL[ni] = g_bl[bidx + ni * 32];
            }
            uint32_t swz = ((uint32_t)((ks * 2 + khalf) ^ rlo)) << 4;
            uint32_t AH[4][4];
#pragma unroll
            for (int mi = 0; mi < 4; ++mi)
                ldsm_x4(AH[mi], aA + rowoff + (uint32_t)mi * 2048 + swz);
#pragma unroll
            for (int mi = 0; mi < 4; ++mi)
#pragma unroll
                for (int ni = 0; ni < 4; ++ni) {
                    mma_f16(acc[mi][ni], AH[mi], BH[ni].x, BH[ni].y);
                    mma_f16(acc[mi][ni], AH[mi], BL[ni].x, BL[ni].y);
                }
        }
        if (k < 7) BAR_ARRIVE(3 + buf, NTHREADS);   // A[buf] + params[buf] reusable
    }

    // ---- epilogue: bias + relu, float2 stores ----
    float2 bv[4];
#pragma unroll
    for (int ni = 0; ni < 4; ++ni) {
        int f = warp_n * 32 + ni * 8 + 2 * tg;
        bv[ni] = *(const float2*)(bias + f);
    }
    size_t rowbase = (((size_t)b * H_ + h) * W_ + w0) * F_;
#pragma unroll
    for (int mi = 0; mi < 4; ++mi) {
        int mA = warp_m * 64 + mi * 16 + g;
#pragma unroll
        for (int ni = 0; ni < 4; ++ni) {
            int f = warp_n * 32 + ni * 8 + 2 * tg;
            float2 oA, oB;
            oA.x = fmaxf(acc[mi][ni][0] + bv[ni].x, 0.f);
            oA.y = fmaxf(acc[mi][ni][1] + bv[ni].y, 0.f);
            oB.x = fmaxf(acc[mi][ni][2] + bv[ni].x, 0.f);
            oB.y = fmaxf(acc[mi][ni][3] + bv[ni].y, 0.f);
            *(float2*)(out + rowbase + (size_t)mA * F_ + f) = oA;
            *(float2*)(out + rowbase + (size_t)(mA + 8) * F_ + f) = oB;
        }
    }
}

extern "C" void kernel_launch(void* const* d_in, const int* in_sizes, int n_in,
                              void* d_out, int out_size) {
    (void)in_sizes; (void)n_in; (void)out_size;
    const float* inp  = (const float*)d_in[0];
    const float* wk   = (const float*)d_in[1];
    const float* bias = (const float*)d_in[2];
    float* out = (float*)d_out;

    init_kernel<<<73, 256>>>(wk);
    dim3 grid(W_ / 128, H_, B_);
    distconv_mma<<<grid, NTHREADS>>>(inp, bias, out);
}

// round 12
// speedup vs baseline: 1.4171x; 1.4171x over previous
#include <cuda_runtime.h>
#include <cuda_fp16.h>
#include <math.h>
#include <stdint.h>

#define H_ 128
#define W_ 256
#define C_ 64
#define F_ 128
#define B_ 4
#define IH 130
#define IW 258

#define NTHREADS 512   // 8 consumer warps (MMA) + 8 producer warps (gather)

// ---------------- device scratch ----------------
__device__ int   g_y0t[H_ * 9];
__device__ int   g_y1t[H_ * 9];
__device__ float g_wyT[H_ * 9];
__device__ float g_wyB[H_ * 9];
__device__ float g_offx[H_ * 9];
// B fragments in mma.m16n8k16 register order: [tap][ks][n8][lane] -> uint2 {b0,b1}, fp16
__device__ uint2 g_bh[9 * 4 * 16 * 32];
__device__ uint2 g_bl[9 * 4 * 16 * 32];

// ---------------- helpers ----------------
__device__ __forceinline__ uint32_t smem_u32(const void* p) {
    uint32_t a;
    asm("{ .reg .u64 t; cvta.to.shared.u64 t, %1; cvt.u32.u64 %0, t; }" : "=r"(a) : "l"(p));
    return a;
}
__device__ __forceinline__ uint32_t pack_half2(__half lo, __half hi) {
    return ((uint32_t)__half_as_ushort(hi) << 16) | __half_as_ushort(lo);
}
__device__ __forceinline__ void ldsm_x4(uint32_t* r, uint32_t addr) {
    asm volatile("ldmatrix.sync.aligned.m8n8.x4.shared.b16 {%0,%1,%2,%3}, [%4];"
                 : "=r"(r[0]), "=r"(r[1]), "=r"(r[2]), "=r"(r[3]) : "r"(addr));
}
__device__ __forceinline__ void mma_f16(float* d, const uint32_t* a, uint32_t b0, uint32_t b1) {
    asm volatile(
        "mma.sync.aligned.m16n8k16.row.col.f32.f16.f16.f32 "
        "{%0,%1,%2,%3}, {%4,%5,%6,%7}, {%8,%9}, {%0,%1,%2,%3};"
        : "+f"(d[0]), "+f"(d[1]), "+f"(d[2]), "+f"(d[3])
        : "r"(a[0]), "r"(a[1]), "r"(a[2]), "r"(a[3]), "r"(b0), "r"(b1));
}
#define BAR_SYNC(id, cnt)   asm volatile("bar.sync %0, %1;"   :: "r"(id), "r"(cnt) : "memory")
#define BAR_ARRIVE(id, cnt) asm volatile("bar.arrive %0, %1;" :: "r"(id), "r"(cnt) : "memory")
#define MEMBAR_CTA()        asm volatile("membar.cta;" ::: "memory")

// barrier ids: full[buf] = 1+buf, empty[buf] = 3+buf, producer-param = 5

// ---------------- combined init: B fragments (blocks 0..71) + distortion tables (block 72) ----
__global__ void init_kernel(const float* __restrict__ wk) {
    if (blockIdx.x < 72) {
        int idx = blockIdx.x * 256 + threadIdx.x;   // < 18432
        int lane = idx & 31;
        int n8 = (idx >> 5) & 15;
        int ks = (idx >> 9) & 3;
        int tap = idx >> 11;
        int g = lane >> 2, tg = lane & 3;
        int n = n8 * 8 + g;
        int kb = ks * 16 + 2 * tg;
        float w0 = wk[(size_t)(tap * 64 + kb) * 128 + n];
        float w1 = wk[(size_t)(tap * 64 + kb + 1) * 128 + n];
        float w2 = wk[(size_t)(tap * 64 + kb + 8) * 128 + n];
        float w3 = wk[(size_t)(tap * 64 + kb + 9) * 128 + n];
        __half h0 = __float2half_rn(w0), h1 = __float2half_rn(w1);
        __half h2 = __float2half_rn(w2), h3 = __float2half_rn(w3);
        g_bh[idx] = make_uint2(pack_half2(h0, h1), pack_half2(h2, h3));
        __half l0 = __float2half_rn(w0 - __half2float(h0));
        __half l1 = __float2half_rn(w1 - __half2float(h1));
        __half l2 = __float2half_rn(w2 - __half2float(h2));
        __half l3 = __float2half_rn(w3 - __half2float(h3));
        g_bl[idx] = make_uint2(pack_half2(l0, l1), pack_half2(l2, l3));
        return;
    }
    // ---- distortion tables (branch-free analytic fp32, see R7) ----
    for (int idx = threadIdx.x; idx < H_ * 9; idx += 256) {
        int h = idx / 9, k = idx % 9;
        const float pi = 3.14159265358979323846f;
        float unit_w = 2.0f * pi / (float)W_;
        float unit_h = pi / (2.0f * (float)H_);
        float rho = tanf(unit_w);
        float phi = ((float)H_ - (float)h) * unit_h;
        float s = sinf(phi), c = cosf(phi);
        const int ra[9] = { 1, 1, 1, 0, 0, 0, -1, -1, -1 };
        const int rb[9] = { -1, 0, 1, -1, 0, 1, -1, 0, 1 };
        float a = (float)ra[k], b = (float)rb[k];
        float t = (-rho * a) / (1.0f - rho * b * s);
        float t2 = t * t;
        float at = t * (1.0f - t2 * (1.0f / 3.0f) + t2 * t2 * (1.0f / 5.0f));
        float off_to_y = at * ((float)W_ / (2.0f * pi));
        float rb1 = rho * b;
        float eps = rb1 * c * (1.0f
                  + rb1 * s * 0.5f
                  + rb1 * rb1 * (1.0f + 2.0f * s * s) * (1.0f / 6.0f)
                  + rb1 * rb1 * rb1 * s * (9.0f + 6.0f * s * s) * (1.0f / 24.0f));
        float off_to_x = -(2.0f * (float)H_ / pi) * eps;

        int dy = k / 3;
        float yf = (float)(h + dy) + off_to_y;
        yf = fminf(fmaxf(yf, 0.0f), (float)(IH - 1));
        int y0 = (int)floorf(yf);
        int y1 = y0 + 1;
        y0 = max(0, min(y0, IH - 1));
        y1 = max(0, min(y1, IH - 1));
        g_y0t[idx] = y0;
        g_y1t[idx] = y1;
        g_wyT[idx] = (float)y1 - yf;
        g_wyB[idx] = yf - (float)y0;
        g_offx[idx] = off_to_x;
    }
}

// ---------------- main fused kernel: warp-specialized producer/consumer (8+8) ----------------
// CTA: 128 pixels x 128 F. Warps 0-7: MMA consumers (warp tile 64x32).
// Warps 8-15: gather producers (full R8 gather throughput).
// Double-buffered A tile AND param tables (same buf index):
//   producer(k): [k>=2: sync empty[buf]] -> params[buf] -> bar5 -> gather A[buf] -> membar -> arrive full[buf]
//   consumer(k): sync full[buf] -> MMA -> arrive empty[buf]
// params[buf] reuse at tap k+2 is fenced by empty[buf] (producers reach it only after
// finishing the tap-k gather, their last read of params[buf]).
__global__ __launch_bounds__(NTHREADS, 1) void distconv_mma(
    const float* __restrict__ inp,
    const float* __restrict__ bias,
    float* __restrict__ out)
{
    __shared__ __align__(128) unsigned char sA[2][16384];  // fp16 A tiles, ldmatrix-swizzled
    __shared__ float4 s_w[2][128];   // per-pixel bilinear weights (pad corners zeroed)
    __shared__ int4   s_a[2][128];   // per-pixel corner byte offsets

    const int tid = threadIdx.x;
    const int wid = tid >> 5, lane = tid & 31;

    const int b = blockIdx.z, h = blockIdx.y;
    const int w0 = blockIdx.x * 128;

    if (wid >= 8) {
        // ================= PRODUCER (warps 8-15, 256 threads) =================
        const char* inpC = (const char*)(inp + (size_t)b * (H_ * W_ * C_));
        const int tp = tid - 256;           // 0..255
        const int chunk = tp & 15;
        const int pgrp = tp >> 4;           // 0..15
        const int cb = chunk * 16;
        const int chalf = (chunk & 1) * 8;
        const int cpair = chunk >> 1;

        for (int k = 0; k < 9; ++k) {
            const int buf = k & 1;
            if (k >= 2) BAR_SYNC(3 + buf, NTHREADS);   // consumers done with A[buf]; all
                                                       // producers done reading params[buf]

            // ---- params: one pixel per thread for first 128 producer threads ----
            if (tp < 128) {
                int t9 = h * 9 + k;
                int dxk = k - (k / 3) * 3;
                float x = (float)(w0 + tp + dxk) + g_offx[t9];
                if (x < 0.f) x += (float)IW;
                if (x > (float)(IW - 1)) x -= (float)IW;
                int x0 = (int)floorf(x);
                int x1 = x0 + 1;
                x0 = max(0, min(x0, IW - 1));
                x1 = max(0, min(x1, IW - 1));
                float wxl = (float)x1 - x, wxr = x - (float)x0;
                int y0 = g_y0t[t9], y1 = g_y1t[t9];
                float wyT = g_wyT[t9], wyB = g_wyB[t9];
                bool vy0 = (y0 >= 1) && (y0 <= H_);
                bool vy1 = (y1 >= 1) && (y1 <= H_);
                bool vx0 = (x0 >= 1) && (x0 <= W_);
                bool vx1 = (x1 >= 1) && (x1 <= W_);
                float4 wv;
                int4 av;
                wv.x = (vy0 && vx0) ? wyT * wxl : 0.f;
                wv.y = (vy0 && vx1) ? wyT * wxr : 0.f;
                wv.z = (vy1 && vx0) ? wyB * wxl : 0.f;
                wv.w = (vy1 && vx1) ? wyB * wxr : 0.f;
                av.x = (vy0 && vx0) ? ((y0 - 1) * W_ + (x0 - 1)) * 256 : 0;
                av.y = (vy0 && vx1) ? ((y0 - 1) * W_ + (x1 - 1)) * 256 : 0;
                av.z = (vy1 && vx0) ? ((y1 - 1) * W_ + (x0 - 1)) * 256 : 0;
                av.w = (vy1 && vx1) ? ((y1 - 1) * W_ + (x1 - 1)) * 256 : 0;
                s_w[buf][tp] = wv;
                s_a[buf][tp] = av;
            }
            BAR_SYNC(5, 256);   // params[buf] visible to all producers

            // ---- gather: coalesced bilinear blend -> fp16 swizzled smem ----
            unsigned char* sAc = sA[buf];
#pragma unroll
            for (int it = 0; it < 8; ++it) {
                int p = it * 16 + pgrp;
                float4 wv = s_w[buf][p];
                int4 av = s_a[buf][p];
                float4 q0 = *(const float4*)(inpC + av.x + cb);
                float4 q1 = *(const float4*)(inpC + av.y + cb);
                float4 q2 = *(const float4*)(inpC + av.z + cb);
                float4 q3 = *(const float4*)(inpC + av.w + cb);
                float v0 = wv.x * q0.x + wv.y * q1.x + wv.z * q2.x + wv.w * q3.x;
                float v1 = wv.x * q0.y + wv.y * q1.y + wv.z * q2.y + wv.w * q3.y;
                float v2 = wv.x * q0.z + wv.y * q1.z + wv.z * q2.z + wv.w * q3.z;
                float v3 = wv.x * q0.w + wv.y * q1.w + wv.z * q2.w + wv.w * q3.w;
                __half2 hA = __floats2half2_rn(v0, v1);
                __half2 hB = __floats2half2_rn(v2, v3);
                uint32_t addr = (uint32_t)p * 128 + ((uint32_t)(cpair ^ (p & 7)) << 4) + chalf;
                *(uint2*)(sAc + addr) = make_uint2(*(uint32_t*)&hA, *(uint32_t*)&hB);
            }
            MEMBAR_CTA();
            BAR_ARRIVE(1 + buf, NTHREADS);   // A[buf] full
        }
        return;
    }

    // ================= CONSUMER (warps 0-7, 256 threads) =================
    const int warp_m = wid >> 2, warp_n = wid & 3;
    const int g = lane >> 2, tg = lane & 3;

    const uint32_t aA0 = smem_u32(sA[0]), aA1 = smem_u32(sA[1]);
    const uint32_t rowoff = (uint32_t)(warp_m * 64 + (lane & 15)) * 128;
    const int rlo = lane & 7;
    const int khalf = lane >> 4;

    float acc[4][4][4];
#pragma unroll
    for (int mi = 0; mi < 4; ++mi)
#pragma unroll
        for (int ni = 0; ni < 4; ++ni)
#pragma unroll
            for (int q = 0; q < 4; ++q) acc[mi][ni][q] = 0.f;

    for (int k = 0; k < 9; ++k) {
        const int buf = k & 1;
        BAR_SYNC(1 + buf, NTHREADS);   // wait A[buf] full
        const uint32_t aA = buf ? aA1 : aA0;
#pragma unroll
        for (int ks = 0; ks < 4; ++ks) {
            uint2 BH[4], BL[4];
            int bidx = ((k * 4 + ks) * 16 + warp_n * 4) * 32 + lane;
#pragma unroll
            for (int ni = 0; ni < 4; ++ni) {
                BH[ni] = g_bh[bidx + ni * 32];
                BL[ni] = g_bl[bidx + ni * 32];
            }
            uint32_t swz = ((uint32_t)((ks * 2 + khalf) ^ rlo)) << 4;
            uint32_t AH[4][4];
#pragma unroll
            for (int mi = 0; mi < 4; ++mi)
                ldsm_x4(AH[mi], aA + rowoff + (uint32_t)mi * 2048 + swz);
#pragma unroll
            for (int mi = 0; mi < 4; ++mi)
#pragma unroll
                for (int ni = 0; ni < 4; ++ni) {
                    mma_f16(acc[mi][ni], AH[mi], BH[ni].x, BH[ni].y);
                    mma_f16(acc[mi][ni], AH[mi], BL[ni].x, BL[ni].y);
                }
        }
        if (k < 7) BAR_ARRIVE(3 + buf, NTHREADS);   // A[buf] + params[buf] reusable
    }

    // ---- epilogue: bias + relu, float2 stores ----
    float2 bv[4];
#pragma unroll
    for (int ni = 0; ni < 4; ++ni) {
        int f = warp_n * 32 + ni * 8 + 2 * tg;
        bv[ni] = *(const float2*)(bias + f);
    }
    size_t rowbase = (((size_t)b * H_ + h) * W_ + w0) * F_;
#pragma unroll
    for (int mi = 0; mi < 4; ++mi) {
        int mA = warp_m * 64 + mi * 16 + g;
#pragma unroll
        for (int ni = 0; ni < 4; ++ni) {
            int f = warp_n * 32 + ni * 8 + 2 * tg;
            float2 oA, oB;
            oA.x = fmaxf(acc[mi][ni][0] + bv[ni].x, 0.f);
            oA.y = fmaxf(acc[mi][ni][1] + bv[ni].y, 0.f);
            oB.x = fmaxf(acc[mi][ni][2] + bv[ni].x, 0.f);
            oB.y = fmaxf(acc[mi][ni][3] + bv[ni].y, 0.f);
            *(float2*)(out + rowbase + (size_t)mA * F_ + f) = oA;
            *(float2*)(out + rowbase + (size_t)(mA + 8) * F_ + f) = oB;
        }
    }
}

extern "C" void kernel_launch(void* const* d_in, const int* in_sizes, int n_in,
                              void* d_out, int out_size) {
    (void)in_sizes; (void)n_in; (void)out_size;
    const float* inp  = (const float*)d_in[0];
    const float* wk   = (const float*)d_in[1];
    const float* bias = (const float*)d_in[2];
    float* out = (float*)d_out;

    init_kernel<<<73, 256>>>(wk);
    dim3 grid(W_ / 128, H_, B_);
    distconv_mma<<<grid, NTHREADS>>>(inp, bias, out);
}

// round 14
// speedup vs baseline: 1.8229x; 1.2863x over previous
#include <cuda_runtime.h>
#include <cuda_fp16.h>
#include <math.h>
#include <stdint.h>

#define H_ 128
#define W_ 256
#define C_ 64
#define F_ 128
#define B_ 4
#define IH 130
#define IW 258

// ---------------- device scratch ----------------
__device__ int   g_y0t[H_ * 9];
__device__ int   g_y1t[H_ * 9];
__device__ float g_wyT[H_ * 9];
__device__ float g_wyB[H_ * 9];
__device__ float g_offx[H_ * 9];
// B fragments in mma.m16n8k16 register order: [tap][ks][n8][lane] -> uint2 {b0,b1}, fp16
__device__ uint2 g_bh[9 * 4 * 16 * 32];

// ---------------- helpers ----------------
__device__ __forceinline__ uint32_t smem_u32(const void* p) {
    uint32_t a;
    asm("{ .reg .u64 t; cvta.to.shared.u64 t, %1; cvt.u32.u64 %0, t; }" : "=r"(a) : "l"(p));
    return a;
}
__device__ __forceinline__ uint32_t pack_half2(__half lo, __half hi) {
    return ((uint32_t)__half_as_ushort(hi) << 16) | __half_as_ushort(lo);
}
__device__ __forceinline__ void ldsm_x4(uint32_t* r, uint32_t addr) {
    asm volatile("ldmatrix.sync.aligned.m8n8.x4.shared.b16 {%0,%1,%2,%3}, [%4];"
                 : "=r"(r[0]), "=r"(r[1]), "=r"(r[2]), "=r"(r[3]) : "r"(addr));
}
__device__ __forceinline__ void mma_f16(float* d, const uint32_t* a, uint32_t b0, uint32_t b1) {
    asm volatile(
        "mma.sync.aligned.m16n8k16.row.col.f32.f16.f16.f32 "
        "{%0,%1,%2,%3}, {%4,%5,%6,%7}, {%8,%9}, {%0,%1,%2,%3};"
        : "+f"(d[0]), "+f"(d[1]), "+f"(d[2]), "+f"(d[3])
        : "r"(a[0]), "r"(a[1]), "r"(a[2]), "r"(a[3]), "r"(b0), "r"(b1));
}

// ---------------- combined init: B fragments (blocks 0..71) + distortion tables (block 72) ----
__global__ void init_kernel(const float* __restrict__ wk) {
    if (blockIdx.x < 72) {
        int idx = blockIdx.x * 256 + threadIdx.x;   // < 18432
        int lane = idx & 31;
        int n8 = (idx >> 5) & 15;
        int ks = (idx >> 9) & 3;
        int tap = idx >> 11;
        int g = lane >> 2, tg = lane & 3;
        int n = n8 * 8 + g;
        int kb = ks * 16 + 2 * tg;
        float w0 = wk[(size_t)(tap * 64 + kb) * 128 + n];
        float w1 = wk[(size_t)(tap * 64 + kb + 1) * 128 + n];
        float w2 = wk[(size_t)(tap * 64 + kb + 8) * 128 + n];
        float w3 = wk[(size_t)(tap * 64 + kb + 9) * 128 + n];
        __half h0 = __float2half_rn(w0), h1 = __float2half_rn(w1);
        __half h2 = __float2half_rn(w2), h3 = __float2half_rn(w3);
        g_bh[idx] = make_uint2(pack_half2(h0, h1), pack_half2(h2, h3));
        return;
    }
    // ---- distortion tables (branch-free analytic fp32, see R7) ----
    for (int idx = threadIdx.x; idx < H_ * 9; idx += 256) {
        int h = idx / 9, k = idx % 9;
        const float pi = 3.14159265358979323846f;
        float unit_w = 2.0f * pi / (float)W_;
        float unit_h = pi / (2.0f * (float)H_);
        float rho = tanf(unit_w);
        float phi = ((float)H_ - (float)h) * unit_h;
        float s = sinf(phi), c = cosf(phi);
        const int ra[9] = { 1, 1, 1, 0, 0, 0, -1, -1, -1 };
        const int rb[9] = { -1, 0, 1, -1, 0, 1, -1, 0, 1 };
        float a = (float)ra[k], b = (float)rb[k];
        float t = (-rho * a) / (1.0f - rho * b * s);
        float t2 = t * t;
        float at = t * (1.0f - t2 * (1.0f / 3.0f) + t2 * t2 * (1.0f / 5.0f));
        float off_to_y = at * ((float)W_ / (2.0f * pi));
        float rb1 = rho * b;
        float eps = rb1 * c * (1.0f
                  + rb1 * s * 0.5f
                  + rb1 * rb1 * (1.0f + 2.0f * s * s) * (1.0f / 6.0f)
                  + rb1 * rb1 * rb1 * s * (9.0f + 6.0f * s * s) * (1.0f / 24.0f));
        float off_to_x = -(2.0f * (float)H_ / pi) * eps;

        int dy = k / 3;
        float yf = (float)(h + dy) + off_to_y;
        yf = fminf(fmaxf(yf, 0.0f), (float)(IH - 1));
        int y0 = (int)floorf(yf);
        int y1 = y0 + 1;
        y0 = max(0, min(y0, IH - 1));
        y1 = max(0, min(y1, IH - 1));
        g_y0t[idx] = y0;
        g_y1t[idx] = y1;
        g_wyT[idx] = (float)y1 - yf;
        g_wyB[idx] = yf - (float)y0;
        g_offx[idx] = off_to_x;
    }
}

// ---------------- main fused kernel (R8 structure, single fp16 product) ----------------
// CTA: 128 pixels x 128 F. 8 warps: warp_m (2) x warp_n (4); warp tile 64x32.
// Software pipelined across taps: double-buffered A tile + params, ONE sync per tap.
__global__ __launch_bounds__(256, 2) void distconv_mma(
    const float* __restrict__ inp,
    const float* __restrict__ bias,
    float* __restrict__ out)
{
    __shared__ __align__(128) unsigned char sA[2][16384];  // fp16 A tiles, ldmatrix-swizzled
    __shared__ float4 s_w[2][128];   // per-pixel bilinear weights (pad corners zeroed)
    __shared__ int4   s_a[2][128];   // per-pixel corner byte offsets

    const int tid = threadIdx.x;
    const int wid = tid >> 5, lane = tid & 31;
    const int warp_m = wid >> 2, warp_n = wid & 3;
    const int g = lane >> 2, tg = lane & 3;

    const int b = blockIdx.z, h = blockIdx.y;
    const int w0 = blockIdx.x * 128;
    const char* inpC = (const char*)(inp + (size_t)b * (H_ * W_ * C_));

    // gather mapping: 16 lanes per pixel, one 16B chunk each (fully coalesced)
    const int chunk = tid & 15;
    const int pgrp = tid >> 4;
    const int cb = chunk * 16;
    const int chalf = (chunk & 1) * 8;
    const int cpair = chunk >> 1;

    // ldmatrix addressing (A): row = warp_m*64 + mi*16 + (lane&15), khalf = lane>>4
    const uint32_t aA0 = smem_u32(sA[0]), aA1 = smem_u32(sA[1]);
    const uint32_t rowoff = (uint32_t)(warp_m * 64 + (lane & 15)) * 128;
    const int rlo = lane & 7;
    const int khalf = lane >> 4;

    float acc[4][4][4];
#pragma unroll
    for (int mi = 0; mi < 4; ++mi)
#pragma unroll
        for (int ni = 0; ni < 4; ++ni)
#pragma unroll
            for (int q = 0; q < 4; ++q) acc[mi][ni][q] = 0.f;

    // ---- param computation for one tap into buffer bb ----
    auto compute_params = [&](int k, int bb) {
        if (tid < 128) {
            int t9 = h * 9 + k;
            int dxk = k - (k / 3) * 3;
            float x = (float)(w0 + tid + dxk) + g_offx[t9];
            if (x < 0.f) x += (float)IW;
            if (x > (float)(IW - 1)) x -= (float)IW;
            int x0 = (int)floorf(x);
            int x1 = x0 + 1;
            x0 = max(0, min(x0, IW - 1));
            x1 = max(0, min(x1, IW - 1));
            float wxl = (float)x1 - x, wxr = x - (float)x0;
            int y0 = g_y0t[t9], y1 = g_y1t[t9];
            float wyT = g_wyT[t9], wyB = g_wyB[t9];
            bool vy0 = (y0 >= 1) && (y0 <= H_);
            bool vy1 = (y1 >= 1) && (y1 <= H_);
            bool vx0 = (x0 >= 1) && (x0 <= W_);
            bool vx1 = (x1 >= 1) && (x1 <= W_);
            float4 wv;
            int4 av;
            wv.x = (vy0 && vx0) ? wyT * wxl : 0.f;
            wv.y = (vy0 && vx1) ? wyT * wxr : 0.f;
            wv.z = (vy1 && vx0) ? wyB * wxl : 0.f;
            wv.w = (vy1 && vx1) ? wyB * wxr : 0.f;
            av.x = (vy0 && vx0) ? ((y0 - 1) * W_ + (x0 - 1)) * 256 : 0;
            av.y = (vy0 && vx1) ? ((y0 - 1) * W_ + (x1 - 1)) * 256 : 0;
            av.z = (vy1 && vx0) ? ((y1 - 1) * W_ + (x0 - 1)) * 256 : 0;
            av.w = (vy1 && vx1) ? ((y1 - 1) * W_ + (x1 - 1)) * 256 : 0;
            s_w[bb][tid] = wv;
            s_a[bb][tid] = av;
        }
    };

    // prologue: params for tap 0
    compute_params(0, 0);
    __syncthreads();

    for (int k = 0; k < 9; ++k) {
        const int cur = k & 1;
        // ---- gather: coalesced bilinear blend -> fp16 swizzled smem (buffer cur) ----
        unsigned char* sAc = sA[cur];
#pragma unroll
        for (int it = 0; it < 8; ++it) {
            int p = it * 16 + pgrp;
            float4 wv = s_w[cur][p];
            int4 av = s_a[cur][p];
            float4 q0 = *(const float4*)(inpC + av.x + cb);
            float4 q1 = *(const float4*)(inpC + av.y + cb);
            float4 q2 = *(const float4*)(inpC + av.z + cb);
            float4 q3 = *(const float4*)(inpC + av.w + cb);
            float v0 = wv.x * q0.x + wv.y * q1.x + wv.z * q2.x + wv.w * q3.x;
            float v1 = wv.x * q0.y + wv.y * q1.y + wv.z * q2.y + wv.w * q3.y;
            float v2 = wv.x * q0.z + wv.y * q1.z + wv.z * q2.z + wv.w * q3.z;
            float v3 = wv.x * q0.w + wv.y * q1.w + wv.z * q2.w + wv.w * q3.w;
            __half2 hA = __floats2half2_rn(v0, v1);
            __half2 hB = __floats2half2_rn(v2, v3);
            uint32_t addr = (uint32_t)p * 128 + ((uint32_t)(cpair ^ (p & 7)) << 4) + chalf;
            *(uint2*)(sAc + addr) = make_uint2(*(uint32_t*)&hA, *(uint32_t*)&hB);
        }
        // ---- params for next tap (other buffer) ----
        if (k < 8) compute_params(k + 1, cur ^ 1);
        __syncthreads();   // A[cur] + P[next] visible to all

        // ---- MMA phase: 4 k16-steps x 1 product; no trailing sync (pipelined) ----
        const uint32_t aA = cur ? aA1 : aA0;
#pragma unroll
        for (int ks = 0; ks < 4; ++ks) {
            uint2 BH[4];
            int bidx = ((k * 4 + ks) * 16 + warp_n * 4) * 32 + lane;
#pragma unroll
            for (int ni = 0; ni < 4; ++ni)
                BH[ni] = g_bh[bidx + ni * 32];
            uint32_t swz = ((uint32_t)((ks * 2 + khalf) ^ rlo)) << 4;
            uint32_t AH[4][4];
#pragma unroll
            for (int mi = 0; mi < 4; ++mi)
                ldsm_x4(AH[mi], aA + rowoff + (uint32_t)mi * 2048 + swz);
#pragma unroll
            for (int mi = 0; mi < 4; ++mi)
#pragma unroll
                for (int ni = 0; ni < 4; ++ni)
                    mma_f16(acc[mi][ni], AH[mi], BH[ni].x, BH[ni].y);
        }
    }

    // ---- epilogue: bias + relu, float2 stores ----
    float2 bv[4];
#pragma unroll
    for (int ni = 0; ni < 4; ++ni) {
        int f = warp_n * 32 + ni * 8 + 2 * tg;
        bv[ni] = *(const float2*)(bias + f);
    }
    size_t rowbase = (((size_t)b * H_ + h) * W_ + w0) * F_;
#pragma unroll
    for (int mi = 0; mi < 4; ++mi) {
        int mA = warp_m * 64 + mi * 16 + g;
#pragma unroll
        for (int ni = 0; ni < 4; ++ni) {
            int f = warp_n * 32 + ni * 8 + 2 * tg;
            float2 oA, oB;
            oA.x = fmaxf(acc[mi][ni][0] + bv[ni].x, 0.f);
            oA.y = fmaxf(acc[mi][ni][1] + bv[ni].y, 0.f);
            oB.x = fmaxf(acc[mi][ni][2] + bv[ni].x, 0.f);
            oB.y = fmaxf(acc[mi][ni][3] + bv[ni].y, 0.f);
            *(float2*)(out + rowbase + (size_t)mA * F_ + f) = oA;
            *(float2*)(out + rowbase + (size_t)(mA + 8) * F_ + f) = oB;
        }
    }
}

extern "C" void kernel_launch(void* const* d_in, const int* in_sizes, int n_in,
                              void* d_out, int out_size) {
    (void)in_sizes; (void)n_in; (void)out_size;
    const float* inp  = (const float*)d_in[0];
    const float* wk   = (const float*)d_in[1];
    const float* bias = (const float*)d_in[2];
    float* out = (float*)d_out;

    init_kernel<<<73, 256>>>(wk);
    dim3 grid(W_ / 128, H_, B_);
    distconv_mma<<<grid, 256>>>(inp, bias, out);
}

// round 17
// speedup vs baseline: 2.1384x; 1.1731x over previous
#include <cuda_runtime.h>
#include <cuda_fp16.h>
#include <math.h>
#include <stdint.h>

#define H_ 128
#define W_ 256
#define C_ 64
#define F_ 128
#define B_ 4
#define IH 130
#define IW 258

// ---------------- device scratch ----------------
__device__ int   g_y0t[H_ * 9];
__device__ int   g_y1t[H_ * 9];
__device__ float g_wyT[H_ * 9];
__device__ float g_wyB[H_ * 9];
__device__ float g_offx[H_ * 9];
// B fragments in mma.m16n8k16 register order: [tap][ks][n8][lane] -> uint2 {b0,b1}, fp16
__device__ uint2 g_bh[9 * 4 * 16 * 32];

// ---------------- helpers ----------------
__device__ __forceinline__ uint32_t smem_u32(const void* p) {
    uint32_t a;
    asm("{ .reg .u64 t; cvta.to.shared.u64 t, %1; cvt.u32.u64 %0, t; }" : "=r"(a) : "l"(p));
    return a;
}
__device__ __forceinline__ uint32_t pack_half2(__half lo, __half hi) {
    return ((uint32_t)__half_as_ushort(hi) << 16) | __half_as_ushort(lo);
}
__device__ __forceinline__ void ldsm_x4(uint32_t* r, uint32_t addr) {
    asm volatile("ldmatrix.sync.aligned.m8n8.x4.shared.b16 {%0,%1,%2,%3}, [%4];"
                 : "=r"(r[0]), "=r"(r[1]), "=r"(r[2]), "=r"(r[3]) : "r"(addr));
}
__device__ __forceinline__ void mma_f16(float* d, const uint32_t* a, uint32_t b0, uint32_t b1) {
    asm volatile(
        "mma.sync.aligned.m16n8k16.row.col.f32.f16.f16.f32 "
        "{%0,%1,%2,%3}, {%4,%5,%6,%7}, {%8,%9}, {%0,%1,%2,%3};"
        : "+f"(d[0]), "+f"(d[1]), "+f"(d[2]), "+f"(d[3])
        : "r"(a[0]), "r"(a[1]), "r"(a[2]), "r"(a[3]), "r"(b0), "r"(b1));
}

// ---------------- combined init: B fragments (blocks 0..71) + distortion tables (block 72) ----
__global__ void init_kernel(const float* __restrict__ wk) {
    if (blockIdx.x < 72) {
        int idx = blockIdx.x * 256 + threadIdx.x;   // < 18432
        int lane = idx & 31;
        int n8 = (idx >> 5) & 15;
        int ks = (idx >> 9) & 3;
        int tap = idx >> 11;
        int g = lane >> 2, tg = lane & 3;
        int n = n8 * 8 + g;
        int kb = ks * 16 + 2 * tg;
        float w0 = wk[(size_t)(tap * 64 + kb) * 128 + n];
        float w1 = wk[(size_t)(tap * 64 + kb + 1) * 128 + n];
        float w2 = wk[(size_t)(tap * 64 + kb + 8) * 128 + n];
        float w3 = wk[(size_t)(tap * 64 + kb + 9) * 128 + n];
        __half h0 = __float2half_rn(w0), h1 = __float2half_rn(w1);
        __half h2 = __float2half_rn(w2), h3 = __float2half_rn(w3);
        g_bh[idx] = make_uint2(pack_half2(h0, h1), pack_half2(h2, h3));
        return;
    }
    // ---- distortion tables (branch-free analytic fp32, see R7) ----
    for (int idx = threadIdx.x; idx < H_ * 9; idx += 256) {
        int h = idx / 9, k = idx % 9;
        const float pi = 3.14159265358979323846f;
        float unit_w = 2.0f * pi / (float)W_;
        float unit_h = pi / (2.0f * (float)H_);
        float rho = tanf(unit_w);
        float phi = ((float)H_ - (float)h) * unit_h;
        float s = sinf(phi), c = cosf(phi);
        const int ra[9] = { 1, 1, 1, 0, 0, 0, -1, -1, -1 };
        const int rb[9] = { -1, 0, 1, -1, 0, 1, -1, 0, 1 };
        float a = (float)ra[k], b = (float)rb[k];
        float t = (-rho * a) / (1.0f - rho * b * s);
        float t2 = t * t;
        float at = t * (1.0f - t2 * (1.0f / 3.0f) + t2 * t2 * (1.0f / 5.0f));
        float off_to_y = at * ((float)W_ / (2.0f * pi));
        float rb1 = rho * b;
        float eps = rb1 * c * (1.0f
                  + rb1 * s * 0.5f
                  + rb1 * rb1 * (1.0f + 2.0f * s * s) * (1.0f / 6.0f)
                  + rb1 * rb1 * rb1 * s * (9.0f + 6.0f * s * s) * (1.0f / 24.0f));
        float off_to_x = -(2.0f * (float)H_ / pi) * eps;

        int dy = k / 3;
        float yf = (float)(h + dy) + off_to_y;
        yf = fminf(fmaxf(yf, 0.0f), (float)(IH - 1));
        int y0 = (int)floorf(yf);
        int y1 = y0 + 1;
        y0 = max(0, min(y0, IH - 1));
        y1 = max(0, min(y1, IH - 1));
        g_y0t[idx] = y0;
        g_y1t[idx] = y1;
        g_wyT[idx] = (float)y1 - yf;
        g_wyB[idx] = yf - (float)y0;
        g_offx[idx] = off_to_x;
    }
}

// ---------------- main fused kernel (R14 structure + pair-shared gather) ----------------
// CTA: 128 pixels x 128 F. 8 warps: warp_m (2) x warp_n (4); warp tile 64x32.
// Software pipelined across taps: double-buffered A tile + params, ONE sync per tap.
// Gather processes PIXEL PAIRS: adjacent pixels share a corner column per row
// (x0(p+1) == x1(p) except at wrap/clip, detected by exact address equality),
// cutting gather LDG.128 count from 8 to 6 per pair. Arithmetic is unchanged.
__global__ __launch_bounds__(256, 2) void distconv_mma(
    const float* __restrict__ inp,
    const float* __restrict__ bias,
    float* __restrict__ out)
{
    __shared__ __align__(128) unsigned char sA[2][16384];  // fp16 A tiles, ldmatrix-swizzled
    __shared__ float4 s_w[2][128];   // per-pixel bilinear weights (pad corners zeroed)
    __shared__ int4   s_a[2][128];   // per-pixel corner byte offsets

    const int tid = threadIdx.x;
    const int wid = tid >> 5, lane = tid & 31;
    const int warp_m = wid >> 2, warp_n = wid & 3;
    const int g = lane >> 2, tg = lane & 3;

    const int b = blockIdx.z, h = blockIdx.y;
    const int w0 = blockIdx.x * 128;
    const char* inpC = (const char*)(inp + (size_t)b * (H_ * W_ * C_));

    // gather mapping: 16 lanes per pixel-PAIR, one 16B chunk each (fully coalesced)
    const int chunk = tid & 15;
    const int pgrp = tid >> 4;          // 0..15 (pair group)
    const int cb = chunk * 16;
    const int chalf = (chunk & 1) * 8;
    const int cpair = chunk >> 1;

    // ldmatrix addressing (A): row = warp_m*64 + mi*16 + (lane&15), khalf = lane>>4
    const uint32_t aA0 = smem_u32(sA[0]), aA1 = smem_u32(sA[1]);
    const uint32_t rowoff = (uint32_t)(warp_m * 64 + (lane & 15)) * 128;
    const int rlo = lane & 7;
    const int khalf = lane >> 4;

    float acc[4][4][4];
#pragma unroll
    for (int mi = 0; mi < 4; ++mi)
#pragma unroll
        for (int ni = 0; ni < 4; ++ni)
#pragma unroll
            for (int q = 0; q < 4; ++q) acc[mi][ni][q] = 0.f;

    // ---- param computation for one tap into buffer bb ----
    auto compute_params = [&](int k, int bb) {
        if (tid < 128) {
            int t9 = h * 9 + k;
            int dxk = k - (k / 3) * 3;
            float x = (float)(w0 + tid + dxk) + g_offx[t9];
            if (x < 0.f) x += (float)IW;
            if (x > (float)(IW - 1)) x -= (float)IW;
            int x0 = (int)floorf(x);
            int x1 = x0 + 1;
            x0 = max(0, min(x0, IW - 1));
            x1 = max(0, min(x1, IW - 1));
            float wxl = (float)x1 - x, wxr = x - (float)x0;
            int y0 = g_y0t[t9], y1 = g_y1t[t9];
            float wyT = g_wyT[t9], wyB = g_wyB[t9];
            bool vy0 = (y0 >= 1) && (y0 <= H_);
            bool vy1 = (y1 >= 1) && (y1 <= H_);
            bool vx0 = (x0 >= 1) && (x0 <= W_);
            bool vx1 = (x1 >= 1) && (x1 <= W_);
            float4 wv;
            int4 av;
            wv.x = (vy0 && vx0) ? wyT * wxl : 0.f;
            wv.y = (vy0 && vx1) ? wyT * wxr : 0.f;
            wv.z = (vy1 && vx0) ? wyB * wxl : 0.f;
            wv.w = (vy1 && vx1) ? wyB * wxr : 0.f;
            av.x = (vy0 && vx0) ? ((y0 - 1) * W_ + (x0 - 1)) * 256 : 0;
            av.y = (vy0 && vx1) ? ((y0 - 1) * W_ + (x1 - 1)) * 256 : 0;
            av.z = (vy1 && vx0) ? ((y1 - 1) * W_ + (x0 - 1)) * 256 : 0;
            av.w = (vy1 && vx1) ? ((y1 - 1) * W_ + (x1 - 1)) * 256 : 0;
            s_w[bb][tid] = wv;
            s_a[bb][tid] = av;
        }
    };

    // prologue: params for tap 0
    compute_params(0, 0);
    __syncthreads();

    for (int k = 0; k < 9; ++k) {
        const int cur = k & 1;
        // ---- gather: pair-shared coalesced bilinear blend -> fp16 swizzled smem ----
        unsigned char* sAc = sA[cur];
#pragma unroll
        for (int it = 0; it < 4; ++it) {
            int pr = it * 16 + pgrp;       // pair index 0..63
            int p0 = pr * 2, p1 = p0 + 1;
            float4 wv0 = s_w[cur][p0];
            int4   av0 = s_a[cur][p0];
            float4 wv1 = s_w[cur][p1];
            int4   av1 = s_a[cur][p1];

            // top row (y0): columns av0.x, av0.y(==av1.x typ.), av1.y
            float4 tA = *(const float4*)(inpC + av0.x + cb);
            float4 tB = *(const float4*)(inpC + av0.y + cb);
            float4 tC;
            if (av1.x == av0.y) tC = tB; else tC = *(const float4*)(inpC + av1.x + cb);
            float4 tD = *(const float4*)(inpC + av1.y + cb);
            float s00 = wv0.x * tA.x + wv0.y * tB.x;
            float s01 = wv0.x * tA.y + wv0.y * tB.y;
            float s02 = wv0.x * tA.z + wv0.y * tB.z;
            float s03 = wv0.x * tA.w + wv0.y * tB.w;
            float s10 = wv1.x * tC.x + wv1.y * tD.x;
            float s11 = wv1.x * tC.y + wv1.y * tD.y;
            float s12 = wv1.x * tC.z + wv1.y * tD.z;
            float s13 = wv1.x * tC.w + wv1.y * tD.w;

            // bottom row (y1)
            float4 bA = *(const float4*)(inpC + av0.z + cb);
            float4 bB = *(const float4*)(inpC + av0.w + cb);
            float4 bC;
            if (av1.z == av0.w) bC = bB; else bC = *(const float4*)(inpC + av1.z + cb);
            float4 bD = *(const float4*)(inpC + av1.w + cb);
            s00 += wv0.z * bA.x + wv0.w * bB.x;
            s01 += wv0.z * bA.y + wv0.w * bB.y;
            s02 += wv0.z * bA.z + wv0.w * bB.z;
            s03 += wv0.z * bA.w + wv0.w * bB.w;
            s10 += wv1.z * bC.x + wv1.w * bD.x;
            s11 += wv1.z * bC.y + wv1.w * bD.y;
            s12 += wv1.z * bC.z + wv1.w * bD.z;
            s13 += wv1.z * bC.w + wv1.w * bD.w;

            __half2 h0A = __floats2half2_rn(s00, s01);
            __half2 h0B = __floats2half2_rn(s02, s03);
            __half2 h1A = __floats2half2_rn(s10, s11);
            __half2 h1B = __floats2half2_rn(s12, s13);
            uint32_t addr0 = (uint32_t)p0 * 128 + ((uint32_t)(cpair ^ (p0 & 7)) << 4) + chalf;
            uint32_t addr1 = (uint32_t)p1 * 128 + ((uint32_t)(cpair ^ (p1 & 7)) << 4) + chalf;
            *(uint2*)(sAc + addr0) = make_uint2(*(uint32_t*)&h0A, *(uint32_t*)&h0B);
            *(uint2*)(sAc + addr1) = make_uint2(*(uint32_t*)&h1A, *(uint32_t*)&h1B);
        }
        // ---- params for next tap (other buffer) ----
        if (k < 8) compute_params(k + 1, cur ^ 1);
        __syncthreads();   // A[cur] + P[next] visible to all

        // ---- MMA phase: 4 k16-steps x 1 product; no trailing sync (pipelined) ----
        const uint32_t aA = cur ? aA1 : aA0;
#pragma unroll
        for (int ks = 0; ks < 4; ++ks) {
            uint2 BH[4];
            int bidx = ((k * 4 + ks) * 16 + warp_n * 4) * 32 + lane;
#pragma unroll
            for (int ni = 0; ni < 4; ++ni)
                BH[ni] = g_bh[bidx + ni * 32];
            uint32_t swz = ((uint32_t)((ks * 2 + khalf) ^ rlo)) << 4;
            uint32_t AH[4][4];
#pragma unroll
            for (int mi = 0; mi < 4; ++mi)
                ldsm_x4(AH[mi], aA + rowoff + (uint32_t)mi * 2048 + swz);
#pragma unroll
            for (int mi = 0; mi < 4; ++mi)
#pragma unroll
                for (int ni = 0; ni < 4; ++ni)
                    mma_f16(acc[mi][ni], AH[mi], BH[ni].x, BH[ni].y);
        }
    }

    // ---- epilogue: bias + relu, float2 stores ----
    float2 bv[4];
#pragma unroll
    for (int ni = 0; ni < 4; ++ni) {
        int f = warp_n * 32 + ni * 8 + 2 * tg;
        bv[ni] = *(const float2*)(bias + f);
    }
    size_t rowbase = (((size_t)b * H_ + h) * W_ + w0) * F_;
#pragma unroll
    for (int mi = 0; mi < 4; ++mi) {
        int mA = warp_m * 64 + mi * 16 + g;
#pragma unroll
        for (int ni = 0; ni < 4; ++ni) {
            int f = warp_n * 32 + ni * 8 + 2 * tg;
            float2 oA, oB;
            oA.x = fmaxf(acc[mi][ni][0] + bv[ni].x, 0.f);
            oA.y = fmaxf(acc[mi][ni][1] + bv[ni].y, 0.f);
            oB.x = fmaxf(acc[mi][ni][2] + bv[ni].x, 0.f);
            oB.y = fmaxf(acc[mi][ni][3] + bv[ni].y, 0.f);
            *(float2*)(out + rowbase + (size_t)mA * F_ + f) = oA;
            *(float2*)(out + rowbase + (size_t)(mA + 8) * F_ + f) = oB;
        }
    }
}

extern "C" void kernel_launch(void* const* d_in, const int* in_sizes, int n_in,
                              void* d_out, int out_size) {
    (void)in_sizes; (void)n_in; (void)out_size;
    const float* inp  = (const float*)d_in[0];
    const float* wk   = (const float*)d_in[1];
    const float* bias = (const float*)d_in[2];
    float* out = (float*)d_out;

    init_kernel<<<73, 256>>>(wk);
    dim3 grid(W_ / 128, H_, B_);
    distconv_mma<<<grid, 256>>>(inp, bias, out);
}